// round 5
// baseline (speedup 1.0000x reference)
#include <cuda_runtime.h>
#include <cstdint>

#define BB    2048
#define TSEQ  512
#define HH    51
#define TTOT  544      // TSEQ + 32 future
#define EPC   16       // batch elements per CTA
#define NCTA  128      // EPC * NCTA == BB
#define NTHR  512      // 2 groups x 64 j x 2 gate-split x 2 k-split
#define MPT   8        // elements per thread (per group)
#define HROW  56       // floats per element row in h arrays (52 used, 16B aligned)
#define NCELL (HH * EPC)   // 816 (j,e) owner cells

// weight layout: addr = q*WQ + j*WJ + ks*16 + gs*8 + kb*4 + p*2 + s
#define WJ     36               // words per (q, j) slot (32 used, conflict-free pad)
#define WQ     (HH * WJ)        // 1836 words per q-slab
#define W_SZ   (7 * WQ)         // 12852 words per weight matrix
#define HD_SZ  (EPC * HROW)     // 896

// z partial buffer: zbuf[e][ks][gate][j] with strides 544 / 272 / 68 / 1
#define ZB_G   68
#define ZB_KS  272
#define ZB_E   544
#define ZB_SZ  (EPC * ZB_E)     // 8704 floats

#define SM_FLOATS (3*W_SZ + 2*HD_SZ + ZB_SZ + 256 + 256 + 256 + 64 + 16)
#define SM_BYTES  (SM_FLOATS * 4)

// ---------------- packed f32x2 helpers ----------------
__device__ __forceinline__ unsigned long long ffma2(unsigned long long a,
                                                    unsigned long long b,
                                                    unsigned long long c) {
    unsigned long long d;
    asm("fma.rn.f32x2 %0, %1, %2, %3;" : "=l"(d) : "l"(a), "l"(b), "l"(c));
    return d;
}
__device__ __forceinline__ float2 unpack2(unsigned long long v) {
    float2 r;
    asm("mov.b64 {%0, %1}, %2;" : "=f"(r.x), "=f"(r.y) : "l"(v));
    return r;
}
__device__ __forceinline__ float sigf(float x) {
    return __fdividef(1.0f, 1.0f + __expf(-x));
}
__device__ __forceinline__ float tanhf_fast(float x) {
    return __fdividef(2.0f, 1.0f + __expf(-2.0f * x)) - 1.0f;
}

// acc{A,B}[m] += W[j, gates(2gs..2gs+1), k-half(ks)] . h[e0+m, k-half(ks)]
__device__ __forceinline__ void matvec_acc(const float* __restrict__ Wthr,
                                           const float* __restrict__ hthr,
                                           unsigned long long aA[MPT],
                                           unsigned long long aB[MPT]) {
#pragma unroll
    for (int q = 0; q < 7; q++) {            // q covers 4 k of my half
        ulonglong2 w0 = *(const ulonglong2*)(Wthr + q * WQ);      // kb0: {gA},{gB}
        ulonglong2 w1 = *(const ulonglong2*)(Wthr + q * WQ + 4);  // kb1: {gA},{gB}
#pragma unroll
        for (int m = 0; m < MPT; m++) {
            ulonglong2 hp = *(const ulonglong2*)(hthr + m * HROW + q * 4);
            aA[m] = ffma2(w0.x, hp.x, aA[m]);
            aB[m] = ffma2(w0.y, hp.x, aB[m]);
            aA[m] = ffma2(w1.x, hp.y, aA[m]);
            aB[m] = ffma2(w1.y, hp.y, aB[m]);
        }
    }
}

__global__ void __launch_bounds__(NTHR, 1)
lstm_seq_kernel(const float* __restrict__ input,
                const float* __restrict__ Wih1, const float* __restrict__ Whh1,
                const float* __restrict__ bih1, const float* __restrict__ bhh1,
                const float* __restrict__ Wih2, const float* __restrict__ Whh2,
                const float* __restrict__ bih2, const float* __restrict__ bhh2,
                const float* __restrict__ Wlin, const float* __restrict__ blin,
                float* __restrict__ out) {
    extern __shared__ float sm[];
    float* W1    = sm;                 // k-split weight layout (see defines)
    float* W2i   = W1  + W_SZ;
    float* W2h   = W2i + W_SZ;
    float* hd1   = W2h + W_SZ;         // [16][56]
    float* hd2   = hd1 + HD_SZ;        // [16][56]
    float* zbuf  = hd2 + HD_SZ;        // [16][2][4][68]
    float* wih1q = zbuf + ZB_SZ;       // [64][4]
    float* b1q   = wih1q + 256;        // [64][4]
    float* b2q   = b1q   + 256;        // [64][4]
    float* wlin  = b2q   + 256;        // [64]
    float* outb  = wlin  + 64;         // [16]

    const int tid = threadIdx.x;
    const int g   = tid >> 8;            // group 0..1 (8 elements each)
    const int r   = tid & 255;
    const int j   = r >> 2;              // hidden unit 0..63 (active < 51)
    const int gs  = (r >> 1) & 1;        // gate split: 0 -> (i,f), 1 -> (g,o)
    const int ks  = r & 1;               // k split: 0 -> k[0..25], 1 -> k[26..50]
    const int jj  = (j < HH) ? j : (HH - 1);
    const int b0  = blockIdx.x * EPC;
    const int e0  = g * MPT;

    // ---------- one-time init ----------
    for (int idx = tid; idx < 3 * W_SZ; idx += NTHR) W1[idx] = 0.f;
    __syncthreads();
    for (int idx = tid; idx < 7 * HH * 4; idx += NTHR) {
        int q   = idx / (HH * 4);
        int rem = idx - q * (HH * 4);
        int jr  = rem >> 2;
        int kss = (rem >> 1) & 1;
        int gss = rem & 1;
        int o   = q * WQ + jr * WJ + kss * 16 + gss * 8;
#pragma unroll
        for (int kb = 0; kb < 2; kb++) {
#pragma unroll
            for (int p = 0; p < 2; p++) {
#pragma unroll
                for (int s = 0; s < 2; s++) {
                    int k  = (kss ? 24 : 0) + 4 * q + 2 * kb + s;
                    bool ok = kss ? (k >= 26 && k < HH) : (k < 26);
                    int gg = gss * 2 + p;
                    int rr = gg * HH + jr;
                    int oo = o + kb * 4 + p * 2 + s;
                    W1 [oo] = ok ? Whh1[rr * HH + k] : 0.f;
                    W2i[oo] = ok ? Wih2[rr * HH + k] : 0.f;
                    W2h[oo] = ok ? Whh2[rr * HH + k] : 0.f;
                }
            }
        }
    }
    if (tid < 64) {
#pragma unroll
        for (int gg = 0; gg < 4; gg++) {
            bool ok = tid < HH;
            wih1q[tid * 4 + gg] = ok ? Wih1[gg * HH + tid] : 0.f;
            b1q  [tid * 4 + gg] = ok ? (bih1[gg * HH + tid] + bhh1[gg * HH + tid]) : 0.f;
            b2q  [tid * 4 + gg] = ok ? (bih2[gg * HH + tid] + bhh2[gg * HH + tid]) : 0.f;
        }
        wlin[tid] = (tid < HH) ? Wlin[tid] : 0.f;
    }
    for (int idx = tid; idx < 2 * HD_SZ; idx += NTHR) hd1[idx] = 0.f;
    const float blin_r = blin[0];
    __syncthreads();

    // matvec-side pointers
    const float* W1t  = W1  + jj * WJ + ks * 16 + gs * 8;
    const float* W2it = W2i + jj * WJ + ks * 16 + gs * 8;
    const float* W2ht = W2h + jj * WJ + ks * 16 + gs * 8;
    const float* hd1t = hd1 + e0 * HROW + ks * 24;    // k-half offset (16B aligned)
    const float* hd2t = hd2 + e0 * HROW + ks * 24;
    float* zbA = zbuf + ks * ZB_KS + gs * 2 * ZB_G + j;   // gate 2gs slot; +ZB_G = 2gs+1

    // owner-side state: cells (j,e) = e*51 + j; cell0 = tid, cell1 = tid + 512
    const int  cell0 = tid;
    const bool own0  = (cell0 < NCELL);
    const bool own1  = (cell0 + NTHR < NCELL);      // tid < 304
    const int  eo0   = cell0 / HH,           jo0 = cell0 - eo0 * HH;
    const int  eo1   = (cell0 + NTHR) / HH,  jo1 = (cell0 + NTHR) - ((cell0 + NTHR) / HH) * HH;
    float4 b1o[2], b2o[2], wxo[2];
    float  wlo[2];
    float  c1o[2] = {0.f, 0.f}, c2o[2] = {0.f, 0.f};
    {
        int jA = own0 ? jo0 : 0, jB = own1 ? jo1 : 0;
        b1o[0] = *(const float4*)(b1q + jA * 4);   b1o[1] = *(const float4*)(b1q + jB * 4);
        b2o[0] = *(const float4*)(b2q + jA * 4);   b2o[1] = *(const float4*)(b2q + jB * 4);
        wxo[0] = *(const float4*)(wih1q + jA * 4); wxo[1] = *(const float4*)(wih1q + jB * 4);
        wlo[0] = wlin[jA]; wlo[1] = wlin[jB];
    }
    const int eos[2] = {eo0, eo1};
    const int jos[2] = {own0 ? jo0 : 0, own1 ? jo1 : 0};
    const bool owns[2] = {own0, own1};

    // ---------- sequential scan ----------
    for (int t = 0; t < TTOT; t++) {
        // loop-top: owners fetch x (gmem during teacher forcing, outb for feedback)
        float xo[2];
#pragma unroll
        for (int u = 0; u < 2; u++) {
            if (owns[u])
                xo[u] = (t < TSEQ) ? input[(size_t)(b0 + eos[u]) * TSEQ + t]
                                   : outb[eos[u]];
        }

        // ---- layer 1 matvec (reads old hd1) ----
        unsigned long long aA[MPT], aB[MPT];
#pragma unroll
        for (int m = 0; m < MPT; m++) { aA[m] = 0ULL; aB[m] = 0ULL; }
        matvec_acc(W1t, hd1t, aA, aB);
#pragma unroll
        for (int m = 0; m < MPT; m++) {
            float2 va = unpack2(aA[m]);
            float2 vb = unpack2(aB[m]);
            zbA[(e0 + m) * ZB_E]        = va.x + va.y;
            zbA[(e0 + m) * ZB_E + ZB_G] = vb.x + vb.y;
        }
        __syncthreads();                                  // B1: zbuf(L1) ready

        // ---- layer 1 combine (owners only, once per cell) ----
        float h1n[2];
#pragma unroll
        for (int u = 0; u < 2; u++) {
            if (owns[u]) {
                const float* zc = zbuf + eos[u] * ZB_E + jos[u];
                float zi = zc[0]        + zc[ZB_KS]          + b1o[u].x + wxo[u].x * xo[u];
                float zf = zc[ZB_G]     + zc[ZB_KS + ZB_G]   + b1o[u].y + wxo[u].y * xo[u];
                float zg = zc[2 * ZB_G] + zc[ZB_KS + 2*ZB_G] + b1o[u].z + wxo[u].z * xo[u];
                float zo = zc[3 * ZB_G] + zc[ZB_KS + 3*ZB_G] + b1o[u].w + wxo[u].w * xo[u];
                float ig = sigf(zi), fg = sigf(zf);
                float gg = tanhf_fast(zg), og = sigf(zo);
                c1o[u] = fg * c1o[u] + ig * gg;
                h1n[u] = og * tanhf_fast(c1o[u]);
                hd1[eos[u] * HROW + jos[u]] = h1n[u];
            }
        }
        if (tid < EPC) outb[tid] = blin_r;                // re-init output accumulator
        __syncthreads();                                  // B2: new hd1 + zbuf free

        // ---- layer 2 matvecs (read new hd1, old hd2) ----
#pragma unroll
        for (int m = 0; m < MPT; m++) { aA[m] = 0ULL; aB[m] = 0ULL; }
        matvec_acc(W2it, hd1t, aA, aB);
        matvec_acc(W2ht, hd2t, aA, aB);
#pragma unroll
        for (int m = 0; m < MPT; m++) {
            float2 va = unpack2(aA[m]);
            float2 vb = unpack2(aB[m]);
            zbA[(e0 + m) * ZB_E]        = va.x + va.y;
            zbA[(e0 + m) * ZB_E + ZB_G] = vb.x + vb.y;
        }
        __syncthreads();                                  // B3: zbuf(L2) ready

        // ---- layer 2 combine + output ----
#pragma unroll
        for (int u = 0; u < 2; u++) {
            if (owns[u]) {
                const float* zc = zbuf + eos[u] * ZB_E + jos[u];
                float zi = zc[0]        + zc[ZB_KS]          + b2o[u].x;
                float zf = zc[ZB_G]     + zc[ZB_KS + ZB_G]   + b2o[u].y;
                float zg = zc[2 * ZB_G] + zc[ZB_KS + 2*ZB_G] + b2o[u].z;
                float zo = zc[3 * ZB_G] + zc[ZB_KS + 3*ZB_G] + b2o[u].w;
                float ig = sigf(zi), fg = sigf(zf);
                float gg = tanhf_fast(zg), og = sigf(zo);
                c2o[u] = fg * c2o[u] + ig * gg;
                float h2 = og * tanhf_fast(c2o[u]);
                hd2[eos[u] * HROW + jos[u]] = h2;
                atomicAdd(&outb[eos[u]], wlo[u] * h2);
            }
        }
        __syncthreads();                                  // B4: outb + hd2 complete
        if (tid < EPC)
            out[(size_t)(b0 + tid) * TTOT + t] = outb[tid];
    }
}

extern "C" void kernel_launch(void* const* d_in, const int* in_sizes, int n_in,
                              void* d_out, int out_size) {
    const float* input = (const float*)d_in[0];
    const float* Wih1  = (const float*)d_in[1];
    const float* Whh1  = (const float*)d_in[2];
    const float* bih1  = (const float*)d_in[3];
    const float* bhh1  = (const float*)d_in[4];
    const float* Wih2  = (const float*)d_in[5];
    const float* Whh2  = (const float*)d_in[6];
    const float* bih2  = (const float*)d_in[7];
    const float* bhh2  = (const float*)d_in[8];
    const float* Wlin  = (const float*)d_in[9];
    const float* blin  = (const float*)d_in[10];
    // d_in[11] = "future" (=32), baked in as a constant.

    cudaFuncSetAttribute(lstm_seq_kernel,
                         cudaFuncAttributeMaxDynamicSharedMemorySize, SM_BYTES);
    lstm_seq_kernel<<<NCTA, NTHR, SM_BYTES>>>(input, Wih1, Whh1, bih1, bhh1,
                                              Wih2, Whh2, bih2, bhh2,
                                              Wlin, blin, (float*)d_out);
}

// round 6
// speedup vs baseline: 1.4359x; 1.4359x over previous
#include <cuda_runtime.h>
#include <cstdint>

#define BB    2048
#define TSEQ  512
#define HH    51
#define TTOT  544      // TSEQ + 32 future
#define EPC   16       // batch elements per CTA
#define NCTA  128
#define NTHR  768      // 3 classes x (2 groups x 64 j x 2 gate-split)
#define MPT   8        // elements per thread
#define WROW  232      // floats per j-row (208 used; 232%32==8 -> conflict-free LDS.128)
#define HROW  56       // floats per element row in h buffers

#define W_SZ   (51 * WROW)      // 11832 floats per weight matrix
#define HD_SZ  (EPC * HROW)     // 896

// zbuf: partial z from mv2h class -> mv2i class. zbuf[e][gate][j]
#define ZG     72               // 2*72 mod 32 == 16 -> conflict-free STS/LDS
#define ZE     (4 * ZG)         // 288
#define ZB_SZ  (EPC * ZE)       // 4608

#define SM_FLOATS (3*W_SZ + 4*HD_SZ + ZB_SZ + 256 + 256 + 256 + 64 + 16 + 32)
#define SM_BYTES  (SM_FLOATS * 4)

// ---------------- packed f32x2 helpers ----------------
__device__ __forceinline__ unsigned long long ffma2(unsigned long long a,
                                                    unsigned long long b,
                                                    unsigned long long c) {
    unsigned long long d;
    asm("fma.rn.f32x2 %0, %1, %2, %3;" : "=l"(d) : "l"(a), "l"(b), "l"(c));
    return d;
}
__device__ __forceinline__ float2 unpack2(unsigned long long v) {
    float2 r;
    asm("mov.b64 {%0, %1}, %2;" : "=f"(r.x), "=f"(r.y) : "l"(v));
    return r;
}
__device__ __forceinline__ float sigf(float x) {
    return __fdividef(1.0f, 1.0f + __expf(-x));
}
__device__ __forceinline__ float tanhf_fast(float x) {
    return __fdividef(2.0f, 1.0f + __expf(-2.0f * x)) - 1.0f;
}

// acc{A,B}[m] += W[j, gates(2gs,2gs+1), :] . h[e0+m, :]   (k-paired f32x2, full k)
__device__ __forceinline__ void matvec_acc(const float* __restrict__ Wrow,
                                           const float* __restrict__ hbase,
                                           unsigned long long aA[MPT],
                                           unsigned long long aB[MPT]) {
#pragma unroll
    for (int q = 0; q < 13; q++) {          // q covers k = 4q .. 4q+3
        ulonglong2 wa = *(const ulonglong2*)(Wrow + q * 16);      // k-pair {4q,4q+1}
        ulonglong2 wb = *(const ulonglong2*)(Wrow + q * 16 + 8);  // k-pair {4q+2,4q+3}
#pragma unroll
        for (int m = 0; m < MPT; m++) {
            ulonglong2 hp = *(const ulonglong2*)(hbase + m * HROW + q * 4);
            aA[m] = ffma2(wa.x, hp.x, aA[m]);
            aB[m] = ffma2(wa.y, hp.x, aB[m]);
            aA[m] = ffma2(wb.x, hp.y, aA[m]);
            aB[m] = ffma2(wb.y, hp.y, aB[m]);
        }
    }
}

__global__ void __launch_bounds__(NTHR, 1)
lstm_seq_kernel(const float* __restrict__ input,
                const float* __restrict__ Wih1, const float* __restrict__ Whh1,
                const float* __restrict__ bih1, const float* __restrict__ bhh1,
                const float* __restrict__ Wih2, const float* __restrict__ Whh2,
                const float* __restrict__ bih2, const float* __restrict__ bhh2,
                const float* __restrict__ Wlin, const float* __restrict__ blin,
                float* __restrict__ out) {
    extern __shared__ float sm[];
    float* W1    = sm;                 // gate-paired layout, WROW stride
    float* W2i   = W1  + W_SZ;
    float* W2h   = W2i + W_SZ;
    float* h1b   = W2h + W_SZ;         // [2][16][56] double-buffered h1
    float* h2b   = h1b + 2 * HD_SZ;    // [2][16][56] double-buffered h2
    float* zbuf  = h2b + 2 * HD_SZ;    // [16][4][72]
    float* wih1q = zbuf + ZB_SZ;       // [64][4]
    float* b1q   = wih1q + 256;        // [64][4]
    float* b2q   = b1q   + 256;        // [64][4]
    float* wlin  = b2q   + 256;        // [64]
    float* xbuf  = wlin  + 64;         // [16]
    float* outb  = xbuf  + 16;         // [2][16]

    const int tid = threadIdx.x;
    const int cls = tid >> 8;            // 0: mv1 (L1), 1: mv2i, 2: mv2h
    const int r   = tid & 255;
    const int g   = r >> 7;              // e-group
    const int rr  = r & 127;
    const int j   = rr >> 1;             // hidden unit 0..63 (active < 51)
    const int gs  = rr & 1;              // gate split: 0 -> (i,f), 1 -> (g,o)
    const int jj  = (j < HH) ? j : (HH - 1);
    const int b0  = blockIdx.x * EPC;
    const int e0  = g * MPT;

    // activation constants: a1 = kA / (1 + exp(kmul*z)) + kB (sig | tanh)
    const float kmul = gs ? -2.0f : -1.0f;
    const float kA   = gs ?  2.0f :  1.0f;
    const float kB   = gs ? -1.0f :  0.0f;

    // ---------- one-time init ----------
    for (int idx = tid; idx < 51 * 26; idx += NTHR) {
        int jr = idx / 26;
        int kb = idx - jr * 26;
#pragma unroll
        for (int gg = 0; gg < 4; gg++) {
#pragma unroll
            for (int s = 0; s < 2; s++) {
                int k  = 2 * kb + s;
                int rw = gg * HH + jr;
                bool ok = (k < HH);
                int o = jr * WROW + kb * 8 + gg * 2 + s;
                W1 [o] = ok ? Whh1[rw * HH + k] : 0.f;
                W2i[o] = ok ? Wih2[rw * HH + k] : 0.f;
                W2h[o] = ok ? Whh2[rw * HH + k] : 0.f;
            }
        }
    }
    if (tid < 64) {
#pragma unroll
        for (int gg = 0; gg < 4; gg++) {
            bool ok = tid < HH;
            wih1q[tid * 4 + gg] = ok ? Wih1[gg * HH + tid] : 0.f;
            b1q  [tid * 4 + gg] = ok ? (bih1[gg * HH + tid] + bhh1[gg * HH + tid]) : 0.f;
            b2q  [tid * 4 + gg] = ok ? (bih2[gg * HH + tid] + bhh2[gg * HH + tid]) : 0.f;
        }
        wlin[tid] = (tid < HH) ? Wlin[tid] : 0.f;
    }
    for (int idx = tid; idx < 4 * HD_SZ; idx += NTHR) h1b[idx] = 0.f;
    const float blin_r = blin[0];
    if (tid < 32) outb[tid] = blin_r;
    __syncthreads();

    // per-class constants
    const float* Wt = (cls == 0 ? W1 : (cls == 1 ? W2i : W2h)) + jj * WROW + gs * 4;
    const float2 wxp = *(const float2*)(wih1q + jj * 4 + gs * 2);
    const float2 bp1 = *(const float2*)(b1q   + jj * 4 + gs * 2);
    const float2 bp2 = *(const float2*)(b2q   + jj * 4 + gs * 2);
    const float  wl  = (gs == 0) ? wlin[j] : 0.f;   // wlin[j>=51]==0
    float* zbA = zbuf + gs * 2 * ZG + j;            // my gate 2gs slot; +ZG = 2gs+1

    float cst[MPT];                                 // c1 (cls0) / c2 (cls1)
#pragma unroll
    for (int m = 0; m < MPT; m++) cst[m] = 0.f;

    // ---------- pipelined tick loop: tick tau computes h1(tau) and h2(tau-1) ----------
    for (int tau = 0; tau <= TTOT; tau++) {
        const int pb = tau & 1;
        const float* h1r = h1b + pb * HD_SZ + e0 * HROW;       // h1(tau-1)
        const float* h2r = h2b + pb * HD_SZ + e0 * HROW;       // h2(tau-2)
        float* h1w = h1b + (pb ^ 1) * HD_SZ;                   // h1(tau)
        float* h2w = h2b + (pb ^ 1) * HD_SZ;                   // h2(tau-1)
        float* outp = outb + pb * 16;                          // out(tau-1) accum
        const bool fut = (tau >= TSEQ);

        // stage x(tau) (teacher-forced range only)
        if (tid < EPC && !fut)
            xbuf[tid] = input[(size_t)(b0 + tid) * TSEQ + tau];

        // ---- matvec phase (all classes independent) ----
        unsigned long long aA[MPT], aB[MPT];
#pragma unroll
        for (int m = 0; m < MPT; m++) { aA[m] = 0ULL; aB[m] = 0ULL; }
        if (cls == 0)      matvec_acc(Wt, h1r, aA, aB);
        else if (cls == 1) matvec_acc(Wt, h1r, aA, aB);
        else               matvec_acc(Wt, h2r, aA, aB);

        if (cls == 2) {    // publish W_hh2 . h2 partials
#pragma unroll
            for (int m = 0; m < MPT; m++) {
                float2 va = unpack2(aA[m]);
                float2 vb = unpack2(aB[m]);
                zbA[(e0 + m) * ZE]      = va.x + va.y;
                zbA[(e0 + m) * ZE + ZG] = vb.x + vb.y;
            }
        }
        __syncthreads();                              // B1: zbuf + xbuf ready

        // ---- L2 combine (cls 1): h2(tau-1), out(tau-1) ----
        if (cls == 1 && tau >= 1) {
#pragma unroll
            for (int m = 0; m < MPT; m++) {
                const float* zc = zbuf + (e0 + m) * ZE + j;
                float2 va = unpack2(aA[m]);
                float2 vb = unpack2(aB[m]);
                float zA = va.x + va.y + zc[2 * gs * ZG]       + bp2.x;
                float zB = vb.x + vb.y + zc[(2 * gs + 1) * ZG] + bp2.y;
                float a1 = kA * __fdividef(1.0f, 1.0f + __expf(kmul * zA)) + kB;
                float a2 = sigf(zB);
                float g_r = __shfl_xor_sync(0xffffffffu, a1, 1);
                float o_r = __shfl_xor_sync(0xffffffffu, a2, 1);
                cst[m]  = a2 * cst[m] + a1 * g_r;     // c2, valid at gs0
                float h2n = o_r * tanhf_fast(cst[m]);
                if (gs == 0 && j < HH)
                    h2w[(e0 + m) * HROW + j] = h2n;
                float p = wl * h2n;                   // 0 on gs1 / j>=51
#pragma unroll
                for (int off = 16; off > 0; off >>= 1)
                    p += __shfl_xor_sync(0xffffffffu, p, off);
                if ((rr & 31) == 0) atomicAdd(&outp[e0 + m], p);
            }
        }

        if (fut) __syncthreads();                     // Bx: out(tau-1) final for feedback

        // ---- L1 combine (cls 0): h1(tau) ----
        if (cls == 0) {
#pragma unroll
            for (int m = 0; m < MPT; m++) {
                float xm = fut ? outp[e0 + m] : xbuf[e0 + m];
                float2 va = unpack2(aA[m]);
                float2 vb = unpack2(aB[m]);
                float zA = va.x + va.y + fmaf(wxp.x, xm, bp1.x);
                float zB = vb.x + vb.y + fmaf(wxp.y, xm, bp1.y);
                float a1 = kA * __fdividef(1.0f, 1.0f + __expf(kmul * zA)) + kB;
                float a2 = sigf(zB);
                float g_r = __shfl_xor_sync(0xffffffffu, a1, 1);
                float o_r = __shfl_xor_sync(0xffffffffu, a2, 1);
                cst[m]  = a2 * cst[m] + a1 * g_r;     // c1, valid at gs0
                float h1n = o_r * tanhf_fast(cst[m]);
                if (gs == 0 && j < HH)
                    h1w[(e0 + m) * HROW + j] = h1n;
            }
        }
        if (cls == 2 && r < EPC)                      // reset next tick's out accum
            outb[(pb ^ 1) * 16 + r] = blin_r;
        __syncthreads();                              // B2: tick complete

        if (tau >= 1 && tid < EPC)
            out[(size_t)(b0 + tid) * TTOT + (tau - 1)] = outp[tid];
    }
}

extern "C" void kernel_launch(void* const* d_in, const int* in_sizes, int n_in,
                              void* d_out, int out_size) {
    const float* input = (const float*)d_in[0];
    const float* Wih1  = (const float*)d_in[1];
    const float* Whh1  = (const float*)d_in[2];
    const float* bih1  = (const float*)d_in[3];
    const float* bhh1  = (const float*)d_in[4];
    const float* Wih2  = (const float*)d_in[5];
    const float* Whh2  = (const float*)d_in[6];
    const float* bih2  = (const float*)d_in[7];
    const float* bhh2  = (const float*)d_in[8];
    const float* Wlin  = (const float*)d_in[9];
    const float* blin  = (const float*)d_in[10];
    // d_in[11] = "future" (=32), baked in as a constant.

    cudaFuncSetAttribute(lstm_seq_kernel,
                         cudaFuncAttributeMaxDynamicSharedMemorySize, SM_BYTES);
    lstm_seq_kernel<<<NCTA, NTHR, SM_BYTES>>>(input, Wih1, Whh1, bih1, bhh1,
                                              Wih2, Whh2, bih2, bhh2,
                                              Wlin, blin, (float*)d_out);
}

// round 7
// speedup vs baseline: 1.7887x; 1.2457x over previous
#include <cuda_runtime.h>
#include <cstdint>

#define BB    2048
#define TSEQ  512
#define HH    51
#define TTOT  544      // TSEQ + 32 future
#define NCTA  152      // one CTA per SM on GB300
#define NBIG  72       // first 72 CTAs take 14 elements, remaining 80 take 13
#define EPCMX 14       // max elements per CTA
#define NTHR  256      // 2 groups x 64 j x 2 gate-split
#define MPT   7        // elements per thread (group covers 7; 2 groups = 14)
#define WROW  232      // floats per j-row (208 used; 232 % 32 == 8 => conflict-free)
#define HROW  56       // floats per element row in h arrays

#define W_SZ   (51 * WROW)      // 11832 floats per weight matrix
#define XS_SZ  (EPCMX * TSEQ)   // 7168
#define HD_SZ  (EPCMX * HROW)   // 784
#define SM_FLOATS (3*W_SZ + XS_SZ + 2*HD_SZ + 256 + 256 + 256 + 64 + 16)
#define SM_BYTES  (SM_FLOATS * 4)

// ---------------- packed f32x2 helpers ----------------
__device__ __forceinline__ unsigned long long ffma2(unsigned long long a,
                                                    unsigned long long b,
                                                    unsigned long long c) {
    unsigned long long d;
    asm("fma.rn.f32x2 %0, %1, %2, %3;" : "=l"(d) : "l"(a), "l"(b), "l"(c));
    return d;
}
__device__ __forceinline__ unsigned long long pack2(float lo, float hi) {
    unsigned long long d;
    asm("mov.b64 %0, {%1, %2};" : "=l"(d) : "f"(lo), "f"(hi));
    return d;
}
__device__ __forceinline__ float2 unpack2(unsigned long long v) {
    float2 r;
    asm("mov.b64 {%0, %1}, %2;" : "=f"(r.x), "=f"(r.y) : "l"(v));
    return r;
}
__device__ __forceinline__ float sigf(float x) {
    return __fdividef(1.0f, 1.0f + __expf(-x));
}
__device__ __forceinline__ float tanhf_fast(float x) {
    return __fdividef(2.0f, 1.0f + __expf(-2.0f * x)) - 1.0f;
}

// acc{A,B}[m] += W[j, gates(2gs,2gs+1), :] . h[e0+m, :]   (k-paired f32x2)
__device__ __forceinline__ void matvec_acc(const float* __restrict__ Wrow,
                                           const float* __restrict__ hbase,
                                           unsigned long long aA[MPT],
                                           unsigned long long aB[MPT]) {
#pragma unroll
    for (int q = 0; q < 13; q++) {          // q covers k = 4q .. 4q+3
        ulonglong2 wa = *(const ulonglong2*)(Wrow + q * 16);      // k-pair {4q,4q+1}
        ulonglong2 wb = *(const ulonglong2*)(Wrow + q * 16 + 8);  // k-pair {4q+2,4q+3}
#pragma unroll
        for (int m = 0; m < MPT; m++) {
            ulonglong2 hp = *(const ulonglong2*)(hbase + m * HROW + q * 4);
            aA[m] = ffma2(wa.x, hp.x, aA[m]);
            aB[m] = ffma2(wa.y, hp.x, aB[m]);
            aA[m] = ffma2(wb.x, hp.y, aA[m]);
            aB[m] = ffma2(wb.y, hp.y, aB[m]);
        }
    }
}

__global__ void __launch_bounds__(NTHR, 1)
lstm_seq_kernel(const float* __restrict__ input,
                const float* __restrict__ Wih1, const float* __restrict__ Whh1,
                const float* __restrict__ bih1, const float* __restrict__ bhh1,
                const float* __restrict__ Wih2, const float* __restrict__ Whh2,
                const float* __restrict__ bih2, const float* __restrict__ bhh2,
                const float* __restrict__ Wlin, const float* __restrict__ blin,
                float* __restrict__ out) {
    extern __shared__ float sm[];
    float* W1    = sm;                 // [51][26 kb][4 gates][2 k]
    float* W2i   = W1  + W_SZ;
    float* W2h   = W2i + W_SZ;
    float* xs    = W2h + W_SZ;         // [14][512]
    float* hd1   = xs  + XS_SZ;        // [14][56]
    float* hd2   = hd1 + HD_SZ;        // [14][56]
    float* wih1q = hd2 + HD_SZ;        // [64][4]
    float* b1q   = wih1q + 256;        // [64][4]
    float* b2q   = b1q   + 256;        // [64][4]
    float* wlin  = b2q   + 256;        // [64]
    float* outb  = wlin  + 64;         // [16]

    const int tid = threadIdx.x;
    const int g   = tid >> 7;            // group 0..1 (7 elements each)
    const int r   = tid & 127;
    const int j   = r >> 1;              // hidden unit 0..63 (active < 51)
    const int gs  = r & 1;               // gate split: 0 -> (i,f), 1 -> (g,o)
    const int jj  = (j < HH) ? j : (HH - 1);
    const int cta = blockIdx.x;
    const int big = (cta < NBIG);
    const int epc = big ? 14 : 13;
    const int b0  = big ? cta * 14 : NBIG * 14 + (cta - NBIG) * 13;
    const int e0  = g * MPT;

    // activation constants: a1 = kA / (1 + exp(kmul*z)) + kB
    // gs0: sigmoid; gs1: tanh
    const float kmul = gs ? -2.0f : -1.0f;
    const float kA   = gs ?  2.0f :  1.0f;
    const float kB   = gs ? -1.0f :  0.0f;

    // ---------- one-time init: rearrange weights (k-paired), stage inputs ----------
    for (int idx = tid; idx < 51 * 26; idx += NTHR) {
        int jr = idx / 26;
        int kb = idx - jr * 26;
#pragma unroll
        for (int gg = 0; gg < 4; gg++) {
#pragma unroll
            for (int s = 0; s < 2; s++) {
                int k = 2 * kb + s;
                int rr = gg * 51 + jr;
                bool ok = (k < HH);
                int o = jr * WROW + kb * 8 + gg * 2 + s;
                W1 [o] = ok ? Whh1[rr * 51 + k] : 0.f;
                W2i[o] = ok ? Wih2[rr * 51 + k] : 0.f;
                W2h[o] = ok ? Whh2[rr * 51 + k] : 0.f;
            }
        }
    }
    if (tid < 64) {
#pragma unroll
        for (int gg = 0; gg < 4; gg++) {
            bool ok = tid < HH;
            wih1q[tid * 4 + gg] = ok ? Wih1[gg * 51 + tid] : 0.f;
            b1q  [tid * 4 + gg] = ok ? (bih1[gg * 51 + tid] + bhh1[gg * 51 + tid]) : 0.f;
            b2q  [tid * 4 + gg] = ok ? (bih2[gg * 51 + tid] + bhh2[gg * 51 + tid]) : 0.f;
        }
        wlin[tid] = (tid < HH) ? Wlin[tid] : 0.f;
    }
    for (int idx = tid; idx < XS_SZ; idx += NTHR) {
        int e = idx >> 9, tc = idx & 511;
        xs[idx] = (e < epc) ? input[(size_t)(b0 + e) * TSEQ + tc] : 0.f;
    }
    for (int idx = tid; idx < 2 * HD_SZ; idx += NTHR) hd1[idx] = 0.f;
    if (tid < 16) outb[tid] = 0.f;
    const float blin_r = blin[0];
    __syncthreads();

    float c1[MPT], c2[MPT];
#pragma unroll
    for (int m = 0; m < MPT; m++) { c1[m] = 0.f; c2[m] = 0.f; }

    const float*  W1r  = W1  + jj * WROW + gs * 4;
    const float*  W2ir = W2i + jj * WROW + gs * 4;
    const float*  W2hr = W2h + jj * WROW + gs * 4;
    const float2  wxp  = *(const float2*)(wih1q + jj * 4 + gs * 2);
    const float2  bp1  = *(const float2*)(b1q   + jj * 4 + gs * 2);
    const float2  bp2  = *(const float2*)(b2q   + jj * 4 + gs * 2);
    const float   wl   = (gs == 0) ? wlin[j] : 0.f;   // wlin[j>=51]==0
    const float*  hd1g = hd1 + e0 * HROW;
    const float*  hd2g = hd2 + e0 * HROW;

    // ---------- sequential scan: T teacher-forced + 32 feedback steps ----------
    for (int t = 0; t < TTOT; t++) {
        float xm[MPT];
        if (t < TSEQ) {
#pragma unroll
            for (int m = 0; m < MPT; m++) xm[m] = xs[(e0 + m) * TSEQ + t];
        } else {
#pragma unroll
            for (int m = 0; m < MPT; m++) xm[m] = outb[e0 + m];   // out[t-1]
        }

        // ---- layer 1 ----
        unsigned long long aA[MPT], aB[MPT];
#pragma unroll
        for (int m = 0; m < MPT; m++) {
            aA[m] = pack2(fmaf(wxp.x, xm[m], bp1.x), 0.f);
            aB[m] = pack2(fmaf(wxp.y, xm[m], bp1.y), 0.f);
        }
        matvec_acc(W1r, hd1g, aA, aB);

        float h1n[MPT];
#pragma unroll
        for (int m = 0; m < MPT; m++) {
            float2 va = unpack2(aA[m]);
            float2 vb = unpack2(aB[m]);
            float za = va.x + va.y, zb = vb.x + vb.y;
            float a1 = kA * __fdividef(1.0f, 1.0f + __expf(kmul * za)) + kB; // ig | gg
            float a2 = sigf(zb);                                             // fg | og
            float g_r = __shfl_xor_sync(0xffffffffu, a1, 1);  // gs0 receives gg
            float o_r = __shfl_xor_sync(0xffffffffu, a2, 1);  // gs0 receives og
            c1[m]  = a2 * c1[m] + a1 * g_r;       // valid at gs0
            h1n[m] = o_r * tanhf_fast(c1[m]);     // valid at gs0
        }
        __syncthreads();                                  // S1: old hd1 / outb reads done
        if (gs == 0 && j < HH) {
#pragma unroll
            for (int m = 0; m < MPT; m++)
                hd1[(e0 + m) * HROW + j] = h1n[m];
        }
        if (tid < EPCMX) outb[tid] = blin_r;              // re-init this step's output
        __syncthreads();                                  // S2: new hd1 visible

        // ---- layer 2 ----
#pragma unroll
        for (int m = 0; m < MPT; m++) {
            aA[m] = pack2(bp2.x, 0.f);
            aB[m] = pack2(bp2.y, 0.f);
        }
        matvec_acc(W2ir, hd1g, aA, aB);   // W_ih2 @ h1(new)
        matvec_acc(W2hr, hd2g, aA, aB);   // W_hh2 @ h2(old)

        float h2n[MPT];
#pragma unroll
        for (int m = 0; m < MPT; m++) {
            float2 va = unpack2(aA[m]);
            float2 vb = unpack2(aB[m]);
            float za = va.x + va.y, zb = vb.x + vb.y;
            float a1 = kA * __fdividef(1.0f, 1.0f + __expf(kmul * za)) + kB;
            float a2 = sigf(zb);
            float g_r = __shfl_xor_sync(0xffffffffu, a1, 1);
            float o_r = __shfl_xor_sync(0xffffffffu, a2, 1);
            c2[m]  = a2 * c2[m] + a1 * g_r;
            h2n[m] = o_r * tanhf_fast(c2[m]);
        }
        __syncthreads();                                  // S3: old hd2 reads done
        if (gs == 0 && j < HH) {
#pragma unroll
            for (int m = 0; m < MPT; m++)
                hd2[(e0 + m) * HROW + j] = h2n[m];
        }
        // out[e] = sum_j wlin[j]*h2[j] + blin : warp butterfly + shared atomic
#pragma unroll
        for (int m = 0; m < MPT; m++) {
            float p = wl * h2n[m];                        // wl==0 at gs1 / j>=51
#pragma unroll
            for (int off = 16; off > 0; off >>= 1)
                p += __shfl_xor_sync(0xffffffffu, p, off);
            if ((tid & 31) == 0) atomicAdd(&outb[e0 + m], p);
        }
        __syncthreads();                                  // S4: outb + hd2 complete
        if (tid < epc)
            out[(size_t)(b0 + tid) * TTOT + t] = outb[tid];
    }
}

extern "C" void kernel_launch(void* const* d_in, const int* in_sizes, int n_in,
                              void* d_out, int out_size) {
    const float* input = (const float*)d_in[0];
    const float* Wih1  = (const float*)d_in[1];
    const float* Whh1  = (const float*)d_in[2];
    const float* bih1  = (const float*)d_in[3];
    const float* bhh1  = (const float*)d_in[4];
    const float* Wih2  = (const float*)d_in[5];
    const float* Whh2  = (const float*)d_in[6];
    const float* bih2  = (const float*)d_in[7];
    const float* bhh2  = (const float*)d_in[8];
    const float* Wlin  = (const float*)d_in[9];
    const float* blin  = (const float*)d_in[10];
    // d_in[11] = "future" (=32), baked in as a constant.

    cudaFuncSetAttribute(lstm_seq_kernel,
                         cudaFuncAttributeMaxDynamicSharedMemorySize, SM_BYTES);
    lstm_seq_kernel<<<NCTA, NTHR, SM_BYTES>>>(input, Wih1, Whh1, bih1, bhh1,
                                              Wih2, Whh2, bih2, bhh2,
                                              Wlin, blin, (float*)d_out);
}